// round 4
// baseline (speedup 1.0000x reference)
#include <cuda_runtime.h>

// Detection_78477642432928 — YOLO decode head
// x: (64, 255, 52, 52) f32  ->  out: (64, 8112, 85) f32
// smem is a p-major mirror of the contiguous output block: s[sp*85 + c].

#define G_DIM   52
#define GG      2704          // 52*52
#define NA      3
#define NC      85            // 5 + 80
#define TILE    128
#define NTILES  22            // 21 full tiles + one 16-wide tail
#define NTASKS  (NC * 4)      // 340 warp-tasks: (channel, 32-wide spatial group)

__device__ __forceinline__ float ftanh(float t) {
    float r;
    asm("tanh.approx.f32 %0, %1;" : "=f"(r) : "f"(t));
    return r;
}

// sigmoid(t) = 0.5*tanh(0.5*t) + 0.5   (1 MUFU instead of EX2+RCP)
__device__ __forceinline__ float fsigmoid(float t) {
    return fmaf(0.5f, ftanh(0.5f * t), 0.5f);
}

__device__ __forceinline__ float decode_elem(float tv, int c, int sp,
                                             float aw, float ah) {
    if (c >= 4) {
        return fsigmoid(tv);                       // conf + classes (uniform per warp)
    } else if (c == 0) {
        // (sigmoid+cx)*8 = 4*tanh(t/2) + 8*cx + 4
        return fmaf(4.0f, ftanh(0.5f * tv), fmaf(8.0f, (float)(sp % G_DIM), 4.0f));
    } else if (c == 1) {
        return fmaf(4.0f, ftanh(0.5f * tv), fmaf(8.0f, (float)(sp / G_DIM), 4.0f));
    } else if (c == 2) {
        return __expf(tv) * aw;
    } else {
        return __expf(tv) * ah;
    }
}

__global__ __launch_bounds__(256, 1)
void det_decode_kernel(const float* __restrict__ x, float* __restrict__ out) {
    __shared__ float s[TILE * NC];                 // 10880 floats = 42.5 KB

    const int bx     = blockIdx.x;
    const int tile   = bx % NTILES;
    const int a      = (bx / NTILES) % NA;
    const int b      = bx / (NTILES * NA);
    const int tstart = tile * TILE;
    const int nvalid = (tstart + TILE <= GG) ? TILE : (GG - tstart);   // 128 or 16
    const int w      = threadIdx.x >> 5;
    const int v      = threadIdx.x & 31;

    const float aw = (a == 0) ? 10.0f : ((a == 1) ? 16.0f : 33.0f);
    const float ah = (a == 0) ? 13.0f : ((a == 1) ? 30.0f : 23.0f);

    const float* __restrict__ xin =
        x + (size_t)((b * NA + a) * NC) * GG + tstart;

    // ---- Load + math: warp-task t = (c, m); lane v reads spatial 32*m+v ----
    if (nvalid == TILE) {
        #pragma unroll 4
        for (int t = w; t < NTASKS; t += 8) {
            const int c  = t >> 2;
            const int sl = ((t & 3) << 5) + v;     // 0..127
            const float tv = xin[(size_t)c * GG + sl];
            s[sl * NC + c] = decode_elem(tv, c, tstart + sl, aw, ah);
        }
    } else {
        for (int t = w; t < NTASKS; t += 8) {
            const int c  = t >> 2;
            const int sl = ((t & 3) << 5) + v;
            if (sl < nvalid) {
                const float tv = xin[(size_t)c * GG + sl];
                s[sl * NC + c] = decode_elem(tv, c, tstart + sl, aw, ah);
            }
        }
    }
    __syncthreads();

    // ---- Write: smem mirrors the output block exactly -> linear float4 copy ----
    float* __restrict__ optr =
        out + (size_t)((b * NA + a) * GG + tstart) * NC;
    const int total4 = (nvalid * NC) >> 2;         // 2720 or 340 (exact)
    const float4* __restrict__ s4 = (const float4*)s;
    float4* __restrict__ o4 = (float4*)optr;
    #pragma unroll 4
    for (int i = threadIdx.x; i < total4; i += 256) {
        o4[i] = s4[i];
    }
}

extern "C" void kernel_launch(void* const* d_in, const int* in_sizes, int n_in,
                              void* d_out, int out_size) {
    const float* x = (const float*)d_in[0];
    float* out = (float*)d_out;
    const int B = 64;
    det_decode_kernel<<<B * NA * NTILES, 256>>>(x, out);
}

// round 8
// speedup vs baseline: 1.5241x; 1.5241x over previous
#include <cuda_runtime.h>

// Detection_78477642432928 — YOLO decode head
// x: (64, 255, 52, 52) f32  ->  out: (64, 8112, 85) f32
// One CTA per (b, anchor, grid-row): TILE = 52 spatial positions.
//   gx = p (column within row), gy = tile  -> no mod/div in decode.
// smem: s[c * 53 + p]  (pitch 53 odd -> conflict-free column reads)

#define GG      2704          // 52*52
#define NA      3
#define NC      85
#define TILE    52
#define PITCH   53
#define NT4     (TILE / 4)    // 13 float4 per channel row
#define NTASK   (NC * NT4)    // 1105 float4 load tasks per CTA

__device__ __forceinline__ float ftanh(float t) {
    float r;
    asm("tanh.approx.f32 %0, %1;" : "=f"(r) : "f"(t));
    return r;
}

__global__ __launch_bounds__(128, 12)
void det_decode_kernel(const float* __restrict__ x, float* __restrict__ out) {
    __shared__ float s[NC * PITCH];               // 4505 floats = 18.0 KB

    const int bx   = blockIdx.x;
    const int tile = bx % TILE;                   // grid row gy
    const int a    = (bx / TILE) % NA;
    const int b    = bx / (TILE * NA);

    const float aw = (a == 0) ? 10.0f : ((a == 1) ? 16.0f : 33.0f);
    const float ah = (a == 0) ? 13.0f : ((a == 1) ? 30.0f : 23.0f);
    const float cyterm = fmaf(8.0f, (float)tile, 4.0f);   // 8*gy + 4

    const float* __restrict__ xin =
        x + (size_t)((b * NA + a) * NC) * GG + tile * TILE;

    // ---- Load + decode: 1105 float4 tasks, vectorized coalesced LDG.128 ----
    #pragma unroll 3
    for (int i = threadIdx.x; i < NTASK; i += 128) {
        const int c = i / NT4;                    // channel (const-div by 13)
        const int v = i - c * NT4;                // float4 index within row
        const float4 val = *(const float4*)(xin + (size_t)c * GG + (v << 2));
        float r[4] = {val.x, val.y, val.z, val.w};
        float o[4];
        #pragma unroll
        for (int k = 0; k < 4; k++) {
            const float tv = r[k];
            if (c >= 4) {
                // sigmoid = 0.5*tanh(t/2) + 0.5   (single MUFU)
                o[k] = fmaf(0.5f, ftanh(0.5f * tv), 0.5f);
            } else if (c == 0) {
                // (sigmoid + gx) * 8 = 4*tanh(t/2) + 8*p + 4
                const float p = (float)((v << 2) + k);
                o[k] = fmaf(4.0f, ftanh(0.5f * tv), fmaf(8.0f, p, 4.0f));
            } else if (c == 1) {
                o[k] = fmaf(4.0f, ftanh(0.5f * tv), cyterm);
            } else if (c == 2) {
                o[k] = __expf(tv) * aw;
            } else {
                o[k] = __expf(tv) * ah;
            }
        }
        const int base = c * PITCH + (v << 2);
        s[base + 0] = o[0];
        s[base + 1] = o[1];
        s[base + 2] = o[2];
        s[base + 3] = o[3];
    }
    __syncthreads();

    // ---- Write: warp per output row; conflict-free LDS, coalesced STG ----
    const int w = threadIdx.x >> 5;
    const int v = threadIdx.x & 31;
    float* __restrict__ optr =
        out + (size_t)((b * NA + a) * GG + tile * TILE) * NC;

    #pragma unroll
    for (int j = 0; j < TILE / 4; j++) {          // 13 rows per warp
        const int r = w + (j << 2);
        const float f0 = s[v * PITCH + r];        // channels v
        const float f1 = s[(v + 32) * PITCH + r]; // channels v+32
        float* __restrict__ rb = optr + r * NC;
        rb[v]      = f0;
        rb[32 + v] = f1;
        if (v < NC - 64) {                        // channels v+64 (v < 21)
            rb[64 + v] = s[(v + 64) * PITCH + r];
        }
    }
}

extern "C" void kernel_launch(void* const* d_in, const int* in_sizes, int n_in,
                              void* d_out, int out_size) {
    const float* x = (const float*)d_in[0];
    float* out = (float*)d_out;
    const int B = 64;
    det_decode_kernel<<<B * NA * TILE, 128>>>(x, out);   // 9984 CTAs
}